// round 12
// baseline (speedup 1.0000x reference)
#include <cuda_runtime.h>
#include <cuda_bf16.h>

// ---------------------------------------------------------------------------
// SurvivalGNN: 2-layer GCN (N=50000, D=128, E=800000) + 2 linear heads.
// GEMMs on HMMA (mma.sync m16n8k16 bf16, fp32 acc), 3-product fp32 emulation:
//   A@W ~= Ahi@Whi + Ahi@Wlo + Alo@Whi
// W^T hi/lo precomputed in gmem as padded smem images. CSR gather agg as R10.
// ---------------------------------------------------------------------------

#define NMAX 50000
#define EMAX 800000
#define D 128
#define PADK 136                     // padded K stride (bf16 elems), 272B rows

__device__ int   g_degi  [NMAX];
__device__ int   g_rowptr[NMAX + 1];
__device__ int   g_fill  [NMAX];
__device__ int   g_bsum  [256];
__device__ int   g_csr   [EMAX];
__device__ float g_dinv  [NMAX];
__device__ float g_hs    [NMAX * D];
__device__ float g_agg   [NMAX * D];
__device__ __nv_bfloat16 g_bimg[4 * 128 * PADK];   // {W1hi,W1lo,W2hi,W2lo} images

#define LDSM_X4(r0, r1, r2, r3, a) \
    asm volatile("ldmatrix.sync.aligned.m8n8.x4.shared.b16 {%0,%1,%2,%3}, [%4];" \
        : "=r"(r0), "=r"(r1), "=r"(r2), "=r"(r3) : "r"(a))

#define MMA16816(c, a0, a1, a2, a3, b0, b1) \
    asm volatile("mma.sync.aligned.m16n8k16.row.col.f32.bf16.bf16.f32 " \
        "{%0,%1,%2,%3}, {%4,%5,%6,%7}, {%8,%9}, {%0,%1,%2,%3};" \
        : "+f"((c)[0]), "+f"((c)[1]), "+f"((c)[2]), "+f"((c)[3]) \
        : "r"(a0), "r"(a1), "r"(a2), "r"(a3), "r"(b0), "r"(b1))

__device__ __forceinline__ unsigned smem_u32(const void* p) {
    unsigned a;
    asm("{ .reg .u64 t; cvta.to.shared.u64 t, %1; cvt.u32.u64 %0, t; }"
        : "=r"(a) : "l"(p));
    return a;
}
__device__ __forceinline__ unsigned pack_bf2(float x, float y) {
    __nv_bfloat16 hx = __float2bfloat16(x), hy = __float2bfloat16(y);
    return ((unsigned)__bfloat16_as_ushort(hy) << 16) | __bfloat16_as_ushort(hx);
}

// ---- degree / dinv / CSR (R10-proven) ------------------------------------
__global__ void k_zero(int n) {
    int i = blockIdx.x * blockDim.x + threadIdx.x;
    if (i < n) g_degi[i] = 0;
}
__global__ void k_count_deg(const int* __restrict__ ei, int E) {
    int e = blockIdx.x * blockDim.x + threadIdx.x;
    if (e < E) atomicAdd(&g_degi[ei[E + e]], 1);
}
__global__ void k_scan1(int n) {
    __shared__ int s[256];
    int t = threadIdx.x, i = blockIdx.x * 256 + t;
    int v = (i < n) ? g_degi[i] : 0;
    if (i < n) g_dinv[i] = rsqrtf((float)v + 1.0f);
    s[t] = v; __syncthreads();
    #pragma unroll
    for (int off = 1; off < 256; off <<= 1) {
        int a = (t >= off) ? s[t - off] : 0;
        __syncthreads(); s[t] += a; __syncthreads();
    }
    if (i < n) g_rowptr[i] = s[t] - v;
    if (t == 255) g_bsum[blockIdx.x] = s[255];
}
__global__ void k_scan3(int n, int E, int nb) {
    __shared__ int s[256];
    int t = threadIdx.x, bid = blockIdx.x;
    s[t] = (t < bid && t < nb) ? g_bsum[t] : 0;
    __syncthreads();
    #pragma unroll
    for (int off = 128; off; off >>= 1) {
        if (t < off) s[t] += s[t + off];
        __syncthreads();
    }
    int off0 = s[0];
    int i = bid * 256 + t;
    if (i < n) {
        int r = g_rowptr[i] + off0;
        g_rowptr[i] = r;
        g_fill[i]   = r;
        if (i == 0) g_rowptr[n] = E;
    }
}
__global__ void k_scatter(const int* __restrict__ ei, int E) {
    int e = blockIdx.x * blockDim.x + threadIdx.x;
    if (e < E) {
        int pos = atomicAdd(&g_fill[ei[E + e]], 1);
        g_csr[pos] = ei[e];
    }
}

// ---- W image prep: Wt[n][k] = W[k][n], hi/lo bf16, padded rows -----------
__global__ void k_prep_w(const float* __restrict__ W1, const float* __restrict__ W2) {
    int gid = blockIdx.x * blockDim.x + threadIdx.x;       // 8*256 = 2048
    for (int idx = gid; idx < 2 * 16384; idx += 2048) {
        int l = idx >> 14, i = idx & 16383;
        int k = i >> 7, nn = i & 127;
        float v = (l ? W2 : W1)[i];                        // W[k][nn]
        __nv_bfloat16 hi = __float2bfloat16(v);
        __nv_bfloat16 lo = __float2bfloat16(v - __bfloat162float(hi));
        g_bimg[(2*l+0) * 128 * PADK + nn * PADK + k] = hi;
        g_bimg[(2*l+1) * 128 * PADK + nn * PADK + k] = lo;
    }
}

// ---- HMMA GEMM: out = (act(in) @ W) * dinv, 128 rows/CTA, 8 warps --------
// transform=0: act = identity; transform=1: act = relu(dinv*in + bias)
__global__ void __launch_bounds__(256)
k_mmagemm(const float* __restrict__ in, const float* __restrict__ bias, int transform,
          const __nv_bfloat16* __restrict__ Bhi, const __nv_bfloat16* __restrict__ Blo,
          float* __restrict__ out, int n)
{
    extern __shared__ __nv_bfloat16 sm[];
    // layout (bf16 elems): Ahi[128*PADK], Alo, Bhi, Blo
    __nv_bfloat16* sAhi = sm;
    __nv_bfloat16* sAlo = sm + 128 * PADK;
    __nv_bfloat16* sBhi = sm + 2 * 128 * PADK;
    __nv_bfloat16* sBlo = sm + 3 * 128 * PADK;

    int tid = threadIdx.x, wid = tid >> 5, lane = tid & 31;
    int base = blockIdx.x * 128;

    // ---- A tile: convert to hi/lo bf16 into padded smem ----
    {
        int r = tid >> 1, half = tid & 1;                  // row r, 64 cols
        int row = base + r;
        unsigned* dsthi = (unsigned*)(sAhi + r * PADK + half * 64);
        unsigned* dstlo = (unsigned*)(sAlo + r * PADK + half * 64);
        #pragma unroll 4
        for (int j = 0; j < 16; j++) {
            float4 v = make_float4(0.f, 0.f, 0.f, 0.f);
            if (row < n) {
                v = *(const float4*)(in + (size_t)row * D + half * 64 + j * 4);
                if (transform) {
                    float  di = g_dinv[row];
                    float4 b  = *(const float4*)(bias + half * 64 + j * 4);
                    v.x = fmaxf(fmaf(di, v.x, b.x), 0.0f);
                    v.y = fmaxf(fmaf(di, v.y, b.y), 0.0f);
                    v.z = fmaxf(fmaf(di, v.z, b.z), 0.0f);
                    v.w = fmaxf(fmaf(di, v.w, b.w), 0.0f);
                }
            }
            float hx = __bfloat162float(__float2bfloat16(v.x));
            float hy = __bfloat162float(__float2bfloat16(v.y));
            float hz = __bfloat162float(__float2bfloat16(v.z));
            float hw = __bfloat162float(__float2bfloat16(v.w));
            dsthi[j*2]   = pack_bf2(v.x, v.y);
            dsthi[j*2+1] = pack_bf2(v.z, v.w);
            dstlo[j*2]   = pack_bf2(v.x - hx, v.y - hy);
            dstlo[j*2+1] = pack_bf2(v.z - hz, v.w - hw);
        }
    }
    // ---- B tiles: linear copy of padded images (hi+lo) ----
    {
        const float4* srcs[2] = { (const float4*)Bhi, (const float4*)Blo };
        float4* dsts[2] = { (float4*)sBhi, (float4*)sBlo };
        const int NV = 128 * PADK * 2 / 16;                // 2176 float4 per image
        #pragma unroll
        for (int im = 0; im < 2; im++)
            for (int i = tid; i < NV; i += 256)
                dsts[im][i] = srcs[im][i];
    }
    __syncthreads();

    // ---- mainloop: warp owns rows [wid*16, wid*16+16), all 128 cols ----
    float acc[16][4];
    #pragma unroll
    for (int t = 0; t < 16; t++) {
        acc[t][0] = 0.f; acc[t][1] = 0.f; acc[t][2] = 0.f; acc[t][3] = 0.f;
    }

    int m = lane >> 3, r8 = lane & 7;
    // A lane address: row = wid*16 + (m&1)*8 + r8, col = (m>>1)*8
    unsigned aA = smem_u32(sAhi) +
        (unsigned)(((wid * 16 + (m & 1) * 8 + r8) * PADK + (m >> 1) * 8) * 2);
    // B lane address: row(n) = (m>>1)*8 + r8, col(k) = (m&1)*8
    unsigned aB = smem_u32(sBhi) +
        (unsigned)((((m >> 1) * 8 + r8) * PADK + (m & 1) * 8) * 2);
    const unsigned LO = 128 * PADK * 2;                    // hi->lo byte offset

    for (int ks = 0; ks < 8; ks++) {                       // K-step = 16
        unsigned kb = ks * 32;                             // 16 bf16 = 32B
        unsigned ah0, ah1, ah2, ah3, al0, al1, al2, al3;
        LDSM_X4(ah0, ah1, ah2, ah3, aA + kb);
        LDSM_X4(al0, al1, al2, al3, aA + kb + LO);
        #pragma unroll
        for (int nt = 0; nt < 8; nt++) {                   // 16 cols per iter
            unsigned bB = aB + kb + nt * (unsigned)(16 * PADK * 2);
            unsigned bh0, bh1, bh2, bh3, bl0, bl1, bl2, bl3;
            LDSM_X4(bh0, bh1, bh2, bh3, bB);
            LDSM_X4(bl0, bl1, bl2, bl3, bB + LO);
            MMA16816(acc[2*nt],   ah0, ah1, ah2, ah3, bh0, bh1);
            MMA16816(acc[2*nt+1], ah0, ah1, ah2, ah3, bh2, bh3);
            MMA16816(acc[2*nt],   ah0, ah1, ah2, ah3, bl0, bl1);
            MMA16816(acc[2*nt+1], ah0, ah1, ah2, ah3, bl2, bl3);
            MMA16816(acc[2*nt],   al0, al1, al2, al3, bh0, bh1);
            MMA16816(acc[2*nt+1], al0, al1, al2, al3, bh2, bh3);
        }
    }

    // ---- epilogue: c0/c1 -> row (lane>>2), c2/c3 -> row+8, col (lane&3)*2
    {
        int row0 = base + wid * 16 + (lane >> 2);
        int row1 = row0 + 8;
        float di0 = (row0 < n) ? g_dinv[row0] : 0.f;
        float di1 = (row1 < n) ? g_dinv[row1] : 0.f;
        int cb = (lane & 3) * 2;
        #pragma unroll
        for (int t = 0; t < 16; t++) {
            int col = t * 8 + cb;
            if (row0 < n)
                *(float2*)(out + (size_t)row0 * D + col) =
                    make_float2(acc[t][0] * di0, acc[t][1] * di0);
            if (row1 < n)
                *(float2*)(out + (size_t)row1 * D + col) =
                    make_float2(acc[t][2] * di1, acc[t][3] * di1);
        }
    }
}

// ---- gather body (R10-proven, MLP=8) -------------------------------------
__device__ __forceinline__ float4 gather_rows(float4 acc, int e, int end, int lane)
{
    for (; e + 7 < end; e += 8) {
        int s0 = g_csr[e],   s1 = g_csr[e+1], s2 = g_csr[e+2], s3 = g_csr[e+3];
        int s4 = g_csr[e+4], s5 = g_csr[e+5], s6 = g_csr[e+6], s7 = g_csr[e+7];
        float4 v0 = *(const float4*)(g_hs + (size_t)s0 * D + lane * 4);
        float4 v1 = *(const float4*)(g_hs + (size_t)s1 * D + lane * 4);
        float4 v2 = *(const float4*)(g_hs + (size_t)s2 * D + lane * 4);
        float4 v3 = *(const float4*)(g_hs + (size_t)s3 * D + lane * 4);
        float4 v4 = *(const float4*)(g_hs + (size_t)s4 * D + lane * 4);
        float4 v5 = *(const float4*)(g_hs + (size_t)s5 * D + lane * 4);
        float4 v6 = *(const float4*)(g_hs + (size_t)s6 * D + lane * 4);
        float4 v7 = *(const float4*)(g_hs + (size_t)s7 * D + lane * 4);
        acc.x += ((v0.x + v1.x) + (v2.x + v3.x)) + ((v4.x + v5.x) + (v6.x + v7.x));
        acc.y += ((v0.y + v1.y) + (v2.y + v3.y)) + ((v4.y + v5.y) + (v6.y + v7.y));
        acc.z += ((v0.z + v1.z) + (v2.z + v3.z)) + ((v4.z + v5.z) + (v6.z + v7.z));
        acc.w += ((v0.w + v1.w) + (v2.w + v3.w)) + ((v4.w + v5.w) + (v6.w + v7.w));
    }
    for (; e + 1 < end; e += 2) {
        int s0 = g_csr[e], s1 = g_csr[e+1];
        float4 v0 = *(const float4*)(g_hs + (size_t)s0 * D + lane * 4);
        float4 v1 = *(const float4*)(g_hs + (size_t)s1 * D + lane * 4);
        acc.x += v0.x + v1.x; acc.y += v0.y + v1.y;
        acc.z += v0.z + v1.z; acc.w += v0.w + v1.w;
    }
    if (e < end) {
        int s0 = g_csr[e];
        float4 v0 = *(const float4*)(g_hs + (size_t)s0 * D + lane * 4);
        acc.x += v0.x; acc.y += v0.y; acc.z += v0.z; acc.w += v0.w;
    }
    return acc;
}

__global__ void __launch_bounds__(256)
k_agg(int n)
{
    int w    = (blockIdx.x * blockDim.x + threadIdx.x) >> 5;
    int lane = threadIdx.x & 31;
    if (w >= n) return;
    size_t o = (size_t)w * D + lane * 4;
    float4 acc = *(const float4*)(g_hs + o);
    acc = gather_rows(acc, g_rowptr[w], g_rowptr[w + 1], lane);
    *(float4*)(g_agg + o) = acc;
}

__global__ void __launch_bounds__(256)
k_agg_heads(const float* __restrict__ b2,
            const float* __restrict__ Wt, const float* __restrict__ bt,
            const float* __restrict__ We, const float* __restrict__ be,
            float* __restrict__ out, int n)
{
    int w    = (blockIdx.x * blockDim.x + threadIdx.x) >> 5;
    int lane = threadIdx.x & 31;
    if (w >= n) return;

    size_t o = (size_t)w * D + lane * 4;
    float4 acc = *(const float4*)(g_hs + o);
    acc = gather_rows(acc, g_rowptr[w], g_rowptr[w + 1], lane);

    float  di = g_dinv[w];
    float4 b  = *(const float4*)(b2 + lane * 4);
    float4 h;
    h.x = fmaxf(fmaf(di, acc.x, b.x), 0.0f);
    h.y = fmaxf(fmaf(di, acc.y, b.y), 0.0f);
    h.z = fmaxf(fmaf(di, acc.z, b.z), 0.0f);
    h.w = fmaxf(fmaf(di, acc.w, b.w), 0.0f);

    float4 wt = *(const float4*)(Wt + lane * 4);
    float4 we = *(const float4*)(We + lane * 4);
    float st = h.x*wt.x + h.y*wt.y + h.z*wt.z + h.w*wt.w;
    float ev = h.x*we.x + h.y*we.y + h.z*we.z + h.w*we.w;
    #pragma unroll
    for (int off = 16; off; off >>= 1) {
        st += __shfl_xor_sync(0xFFFFFFFFu, st, off);
        ev += __shfl_xor_sync(0xFFFFFFFFu, ev, off);
    }
    if (lane == 0) {
        out[w]     = st + bt[0];
        out[n + w] = ev + be[0];
    }
}

// ---------------------------------------------------------------------------
extern "C" void kernel_launch(void* const* d_in, const int* in_sizes, int n_in,
                              void* d_out, int out_size)
{
    const float* x   = (const float*)d_in[0];
    const int*   ei  = (const int*)  d_in[1];
    const float* W1  = (const float*)d_in[2];
    const float* b1  = (const float*)d_in[3];
    const float* W2  = (const float*)d_in[4];
    const float* b2  = (const float*)d_in[5];
    const float* Wt  = (const float*)d_in[6];
    const float* bt  = (const float*)d_in[7];
    const float* We  = (const float*)d_in[8];
    const float* be  = (const float*)d_in[9];
    float* out = (float*)d_out;

    int n = in_sizes[0] / D;       // 50000
    int E = in_sizes[1] / 2;       // 800000

    const int T = 256;
    const int GSMEM = 4 * 128 * PADK * 2;   // 4 padded bf16 tiles = 139264 B
    int nb_n = (n + T - 1) / T;
    int nb_e = (E + T - 1) / T;
    int nb_t = (n + 127) / 128;
    int nb_w = (n + 7) / 8;

    __nv_bfloat16* bimg;
    float *hs, *agg;
    cudaGetSymbolAddress((void**)&bimg, g_bimg);
    cudaGetSymbolAddress((void**)&hs,   g_hs);
    cudaGetSymbolAddress((void**)&agg,  g_agg);

    cudaFuncSetAttribute(k_mmagemm, cudaFuncAttributeMaxDynamicSharedMemorySize, GSMEM);

    // W images + normalization + CSR
    k_prep_w   <<<8,    T>>>(W1, W2);
    k_zero     <<<nb_n, T>>>(n);
    k_count_deg<<<nb_e, T>>>(ei, E);
    k_scan1    <<<nb_n, T>>>(n);
    k_scan3    <<<nb_n, T>>>(n, E, nb_n);
    k_scatter  <<<nb_e, T>>>(ei, E);

    // layer 1: HMMA GEMM -> g_hs, aggregate -> g_agg
    k_mmagemm<<<nb_t, T, GSMEM>>>(x, nullptr, 0,
                                  bimg + 0 * 128 * PADK, bimg + 1 * 128 * PADK, hs, n);
    k_agg    <<<nb_w, T>>>(n);

    // layer 2: (relu transform + HMMA GEMM) -> g_hs, aggregate + heads
    k_mmagemm<<<nb_t, T, GSMEM>>>(agg, b1, 1,
                                  bimg + 2 * 128 * PADK, bimg + 3 * 128 * PADK, hs, n);
    k_agg_heads<<<nb_w, T>>>(b2, Wt, bt, We, be, out, n);
}

// round 14
// speedup vs baseline: 1.1942x; 1.1942x over previous
#include <cuda_runtime.h>
#include <cuda_bf16.h>
#include <cuda_fp16.h>

// ---------------------------------------------------------------------------
// SurvivalGNN: 2-layer GCN (N=50000, D=128, E=800000) + 2 linear heads.
//   hs[i]  = (act(in) @ W)[i] * dinv[i]     (scalar blocked GEMM, 8 rows/warp)
//   agg[i] = hs[i] + sum_{e: dst=i} hs[src] (CSR gather, warp/node, MLP=8)
// Messages (hs) stored as fp16 -> gather traffic halved vs fp32.
// ---------------------------------------------------------------------------

#define NMAX 50000
#define EMAX 800000
#define D 128

__device__ int    g_degi  [NMAX];
__device__ int    g_rowptr[NMAX + 1];
__device__ int    g_fill  [NMAX];
__device__ int    g_bsum  [256];
__device__ int    g_csr   [EMAX];
__device__ float  g_dinv  [NMAX];
__device__ __half g_hs    [NMAX * D];      // fp16 messages
__device__ float  g_agg   [NMAX * D];      // fp32 aggregation result

__device__ __forceinline__ unsigned pack_h2(float x, float y) {
    __half2 h = __floats2half2_rn(x, y);
    return *(unsigned*)&h;
}
__device__ __forceinline__ float2 unpack_h2(unsigned u) {
    return __half22float2(*(__half2*)&u);
}

// ---- degree / dinv / CSR (R10-proven) ------------------------------------
__global__ void k_zero(int n) {
    int i = blockIdx.x * blockDim.x + threadIdx.x;
    if (i < n) g_degi[i] = 0;
}
__global__ void k_count_deg(const int* __restrict__ ei, int E) {
    int e = blockIdx.x * blockDim.x + threadIdx.x;
    if (e < E) atomicAdd(&g_degi[ei[E + e]], 1);
}
__global__ void k_scan1(int n) {
    __shared__ int s[256];
    int t = threadIdx.x, i = blockIdx.x * 256 + t;
    int v = (i < n) ? g_degi[i] : 0;
    if (i < n) g_dinv[i] = rsqrtf((float)v + 1.0f);
    s[t] = v; __syncthreads();
    #pragma unroll
    for (int off = 1; off < 256; off <<= 1) {
        int a = (t >= off) ? s[t - off] : 0;
        __syncthreads(); s[t] += a; __syncthreads();
    }
    if (i < n) g_rowptr[i] = s[t] - v;
    if (t == 255) g_bsum[blockIdx.x] = s[255];
}
__global__ void k_scan3(int n, int E, int nb) {
    __shared__ int s[256];
    int t = threadIdx.x, bid = blockIdx.x;
    s[t] = (t < bid && t < nb) ? g_bsum[t] : 0;
    __syncthreads();
    #pragma unroll
    for (int off = 128; off; off >>= 1) {
        if (t < off) s[t] += s[t + off];
        __syncthreads();
    }
    int off0 = s[0];
    int i = bid * 256 + t;
    if (i < n) {
        int r = g_rowptr[i] + off0;
        g_rowptr[i] = r;
        g_fill[i]   = r;
        if (i == 0) g_rowptr[n] = E;
    }
}
__global__ void k_scatter(const int* __restrict__ ei, int E) {
    int e = blockIdx.x * blockDim.x + threadIdx.x;
    if (e < E) {
        int pos = atomicAdd(&g_fill[ei[E + e]], 1);
        g_csr[pos] = ei[e];
    }
}

// ---- scalar GEMM mainloop: 64 rows/block, 8 rows/warp, fp16 output -------
__device__ __forceinline__ void gemm_main(const float (*sx)[D],
                                          const float* __restrict__ W,
                                          __half* __restrict__ out, int base, int n)
{
    int t = threadIdx.x, warp = t >> 5, lane = t & 31;
    int r0 = warp * 8;
    float4 acc[8];
    #pragma unroll
    for (int r = 0; r < 8; r++) acc[r] = make_float4(0.f, 0.f, 0.f, 0.f);

    const float* Wp = W + lane * 4;
    #pragma unroll 4
    for (int k = 0; k < D; k++) {
        float4 w = *(const float4*)(Wp + k * D);
        #pragma unroll
        for (int r = 0; r < 8; r++) {
            float xv = sx[r0 + r][k];
            acc[r].x = fmaf(xv, w.x, acc[r].x);
            acc[r].y = fmaf(xv, w.y, acc[r].y);
            acc[r].z = fmaf(xv, w.z, acc[r].z);
            acc[r].w = fmaf(xv, w.w, acc[r].w);
        }
    }
    #pragma unroll
    for (int r = 0; r < 8; r++) {
        int row = base + r0 + r;
        if (row < n) {
            float di = g_dinv[row];
            uint2 st;
            st.x = pack_h2(acc[r].x * di, acc[r].y * di);
            st.y = pack_h2(acc[r].z * di, acc[r].w * di);
            *(uint2*)(out + (size_t)row * D + lane * 4) = st;
        }
    }
}

// ---- layer 1 GEMM: g_hs = (x @ W1) * dinv --------------------------------
__global__ void __launch_bounds__(256)
k_gemm1(const float* __restrict__ in, const float* __restrict__ W, int n)
{
    __shared__ float sx[64][D];
    int t = threadIdx.x;
    int base = blockIdx.x * 64;
    #pragma unroll
    for (int j = 0; j < 8; j++) {
        int f = j * 256 + t;
        int r = f >> 5, c = f & 31;
        int row = base + r;
        if (row < n)
            *(float4*)&sx[r][c * 4] = *(const float4*)(in + (size_t)row * D + c * 4);
    }
    __syncthreads();
    gemm_main(sx, W, g_hs, base, n);
}

// ---- layer 2 GEMM: reads g_agg, applies relu(dinv*agg+b1), -> g_hs -------
__global__ void __launch_bounds__(256)
k_gemm2(const float* __restrict__ b1, const float* __restrict__ W, int n)
{
    __shared__ float sx[64][D];
    int t = threadIdx.x;
    int base = blockIdx.x * 64;
    #pragma unroll
    for (int j = 0; j < 8; j++) {
        int f = j * 256 + t;
        int r = f >> 5, c = f & 31;
        int row = base + r;
        if (row < n) {
            float  di = g_dinv[row];
            float4 a  = *(const float4*)(g_agg + (size_t)row * D + c * 4);
            float4 b  = *(const float4*)(b1 + c * 4);
            float4 v;
            v.x = fmaxf(fmaf(di, a.x, b.x), 0.0f);
            v.y = fmaxf(fmaf(di, a.y, b.y), 0.0f);
            v.z = fmaxf(fmaf(di, a.z, b.z), 0.0f);
            v.w = fmaxf(fmaf(di, a.w, b.w), 0.0f);
            *(float4*)&sx[r][c * 4] = v;
        }
    }
    __syncthreads();
    gemm_main(sx, W, g_hs, base, n);                   // ping-pong -> g_hs
}

// ---- gather body: fp16 messages, fp32 accumulate, MLP=8 ------------------
__device__ __forceinline__ float4 gather_rows(float4 acc, int e, int end, int lane)
{
    for (; e + 7 < end; e += 8) {
        int s0 = g_csr[e],   s1 = g_csr[e+1], s2 = g_csr[e+2], s3 = g_csr[e+3];
        int s4 = g_csr[e+4], s5 = g_csr[e+5], s6 = g_csr[e+6], s7 = g_csr[e+7];
        uint2 u0 = *(const uint2*)(g_hs + (size_t)s0 * D + lane * 4);
        uint2 u1 = *(const uint2*)(g_hs + (size_t)s1 * D + lane * 4);
        uint2 u2 = *(const uint2*)(g_hs + (size_t)s2 * D + lane * 4);
        uint2 u3 = *(const uint2*)(g_hs + (size_t)s3 * D + lane * 4);
        uint2 u4 = *(const uint2*)(g_hs + (size_t)s4 * D + lane * 4);
        uint2 u5 = *(const uint2*)(g_hs + (size_t)s5 * D + lane * 4);
        uint2 u6 = *(const uint2*)(g_hs + (size_t)s6 * D + lane * 4);
        uint2 u7 = *(const uint2*)(g_hs + (size_t)s7 * D + lane * 4);
        float2 a0, b0;
        a0 = unpack_h2(u0.x); b0 = unpack_h2(u0.y); acc.x += a0.x; acc.y += a0.y; acc.z += b0.x; acc.w += b0.y;
        a0 = unpack_h2(u1.x); b0 = unpack_h2(u1.y); acc.x += a0.x; acc.y += a0.y; acc.z += b0.x; acc.w += b0.y;
        a0 = unpack_h2(u2.x); b0 = unpack_h2(u2.y); acc.x += a0.x; acc.y += a0.y; acc.z += b0.x; acc.w += b0.y;
        a0 = unpack_h2(u3.x); b0 = unpack_h2(u3.y); acc.x += a0.x; acc.y += a0.y; acc.z += b0.x; acc.w += b0.y;
        a0 = unpack_h2(u4.x); b0 = unpack_h2(u4.y); acc.x += a0.x; acc.y += a0.y; acc.z += b0.x; acc.w += b0.y;
        a0 = unpack_h2(u5.x); b0 = unpack_h2(u5.y); acc.x += a0.x; acc.y += a0.y; acc.z += b0.x; acc.w += b0.y;
        a0 = unpack_h2(u6.x); b0 = unpack_h2(u6.y); acc.x += a0.x; acc.y += a0.y; acc.z += b0.x; acc.w += b0.y;
        a0 = unpack_h2(u7.x); b0 = unpack_h2(u7.y); acc.x += a0.x; acc.y += a0.y; acc.z += b0.x; acc.w += b0.y;
    }
    for (; e < end; e++) {
        int s0 = g_csr[e];
        uint2 u0 = *(const uint2*)(g_hs + (size_t)s0 * D + lane * 4);
        float2 a0 = unpack_h2(u0.x), b0 = unpack_h2(u0.y);
        acc.x += a0.x; acc.y += a0.y; acc.z += b0.x; acc.w += b0.y;
    }
    return acc;
}

// ---- aggregation: g_agg[i] = g_hs[i] + sum_nbr g_hs[src]  (fp32 out) -----
__global__ void __launch_bounds__(256)
k_agg(int n)
{
    int w    = (blockIdx.x * blockDim.x + threadIdx.x) >> 5;
    int lane = threadIdx.x & 31;
    if (w >= n) return;
    uint2 su = *(const uint2*)(g_hs + (size_t)w * D + lane * 4);   // self loop
    float2 sa = unpack_h2(su.x), sb = unpack_h2(su.y);
    float4 acc = make_float4(sa.x, sa.y, sb.x, sb.y);
    acc = gather_rows(acc, g_rowptr[w], g_rowptr[w + 1], lane);
    *(float4*)(g_agg + (size_t)w * D + lane * 4) = acc;
}

// ---- final aggregation + heads -------------------------------------------
__global__ void __launch_bounds__(256)
k_agg_heads(const float* __restrict__ b2,
            const float* __restrict__ Wt, const float* __restrict__ bt,
            const float* __restrict__ We, const float* __restrict__ be,
            float* __restrict__ out, int n)
{
    int w    = (blockIdx.x * blockDim.x + threadIdx.x) >> 5;
    int lane = threadIdx.x & 31;
    if (w >= n) return;

    uint2 su = *(const uint2*)(g_hs + (size_t)w * D + lane * 4);   // self loop
    float2 sa = unpack_h2(su.x), sb = unpack_h2(su.y);
    float4 acc = make_float4(sa.x, sa.y, sb.x, sb.y);
    acc = gather_rows(acc, g_rowptr[w], g_rowptr[w + 1], lane);

    float  di = g_dinv[w];
    float4 b  = *(const float4*)(b2 + lane * 4);
    float4 h;
    h.x = fmaxf(fmaf(di, acc.x, b.x), 0.0f);
    h.y = fmaxf(fmaf(di, acc.y, b.y), 0.0f);
    h.z = fmaxf(fmaf(di, acc.z, b.z), 0.0f);
    h.w = fmaxf(fmaf(di, acc.w, b.w), 0.0f);

    float4 wt = *(const float4*)(Wt + lane * 4);
    float4 we = *(const float4*)(We + lane * 4);
    float st = h.x*wt.x + h.y*wt.y + h.z*wt.z + h.w*wt.w;
    float ev = h.x*we.x + h.y*we.y + h.z*we.z + h.w*we.w;
    #pragma unroll
    for (int off = 16; off; off >>= 1) {
        st += __shfl_xor_sync(0xFFFFFFFFu, st, off);
        ev += __shfl_xor_sync(0xFFFFFFFFu, ev, off);
    }
    if (lane == 0) {
        out[w]     = st + bt[0];
        out[n + w] = ev + be[0];
    }
}

// ---------------------------------------------------------------------------
extern "C" void kernel_launch(void* const* d_in, const int* in_sizes, int n_in,
                              void* d_out, int out_size)
{
    const float* x   = (const float*)d_in[0];
    const int*   ei  = (const int*)  d_in[1];
    const float* W1  = (const float*)d_in[2];
    const float* b1  = (const float*)d_in[3];
    const float* W2  = (const float*)d_in[4];
    const float* b2  = (const float*)d_in[5];
    const float* Wt  = (const float*)d_in[6];
    const float* bt  = (const float*)d_in[7];
    const float* We  = (const float*)d_in[8];
    const float* be  = (const float*)d_in[9];
    float* out = (float*)d_out;

    int n = in_sizes[0] / D;       // 50000
    int E = in_sizes[1] / 2;       // 800000

    const int T = 256;
    int nb_n = (n + T - 1) / T;
    int nb_e = (E + T - 1) / T;
    int nb_g = (n + 63) / 64;
    int nb_w = (n + 7) / 8;

    // normalization + CSR
    k_zero     <<<nb_n, T>>>(n);
    k_count_deg<<<nb_e, T>>>(ei, E);
    k_scan1    <<<nb_n, T>>>(n);
    k_scan3    <<<nb_n, T>>>(n, E, nb_n);
    k_scatter  <<<nb_e, T>>>(ei, E);

    // layer 1: GEMM -> g_hs (fp16), aggregate -> g_agg (fp32)
    k_gemm1<<<nb_g, T>>>(x, W1, n);
    k_agg  <<<nb_w, T>>>(n);

    // layer 2: (relu transform + GEMM) -> g_hs, aggregate + heads -> out
    k_gemm2    <<<nb_g, T>>>(b1, W2, n);
    k_agg_heads<<<nb_w, T>>>(b2, Wt, bt, We, be, out, n);
}

// round 15
// speedup vs baseline: 1.2419x; 1.0399x over previous
#include <cuda_runtime.h>
#include <cuda_bf16.h>
#include <cuda_fp16.h>

// ---------------------------------------------------------------------------
// SurvivalGNN: 2-layer GCN (N=50000, D=128, E=800000) + 2 linear heads.
//   m[i]   = (act(in) @ W)[i]                  (fp16 messages, UNSCALED)
//   agg[i] = sum_{src in N(i)+{i}} m[src]*dinv[src]   (scale folded in gather)
//   next   = relu(dinv[i]*agg[i] + b)
// CSR/degree build forked onto a 2nd stream, overlapped with layer-1 GEMM
// (which no longer depends on dinv).
// ---------------------------------------------------------------------------

#define NMAX 50000
#define EMAX 800000
#define D 128

__device__ int    g_degi  [NMAX];
__device__ int    g_rowptr[NMAX + 1];
__device__ int    g_fill  [NMAX];
__device__ int    g_bsum  [256];
__device__ int    g_csr   [EMAX];
__device__ float  g_dinv  [NMAX];
__device__ __half g_hs    [NMAX * D];      // fp16 messages (unscaled)
__device__ float  g_agg   [NMAX * D];      // fp32 aggregation result

__device__ __forceinline__ unsigned pack_h2(float x, float y) {
    __half2 h = __floats2half2_rn(x, y);
    return *(unsigned*)&h;
}
__device__ __forceinline__ float2 unpack_h2(unsigned u) {
    return __half22float2(*(__half2*)&u);
}

// ---- degree / dinv / CSR -------------------------------------------------
__global__ void k_zero(int n) {
    int i = blockIdx.x * blockDim.x + threadIdx.x;
    if (i < n) g_degi[i] = 0;
}
__global__ void k_count_deg(const int* __restrict__ ei, int E) {
    int e = blockIdx.x * blockDim.x + threadIdx.x;
    if (e < E) atomicAdd(&g_degi[ei[E + e]], 1);
}
__global__ void k_scan1(int n) {
    __shared__ int s[256];
    int t = threadIdx.x, i = blockIdx.x * 256 + t;
    int v = (i < n) ? g_degi[i] : 0;
    if (i < n) g_dinv[i] = rsqrtf((float)v + 1.0f);
    s[t] = v; __syncthreads();
    #pragma unroll
    for (int off = 1; off < 256; off <<= 1) {
        int a = (t >= off) ? s[t - off] : 0;
        __syncthreads(); s[t] += a; __syncthreads();
    }
    if (i < n) g_rowptr[i] = s[t] - v;
    if (t == 255) g_bsum[blockIdx.x] = s[255];
}
__global__ void k_scan3(int n, int E, int nb) {
    __shared__ int s[256];
    int t = threadIdx.x, bid = blockIdx.x;
    s[t] = (t < bid && t < nb) ? g_bsum[t] : 0;
    __syncthreads();
    #pragma unroll
    for (int off = 128; off; off >>= 1) {
        if (t < off) s[t] += s[t + off];
        __syncthreads();
    }
    int off0 = s[0];
    int i = bid * 256 + t;
    if (i < n) {
        int r = g_rowptr[i] + off0;
        g_rowptr[i] = r;
        g_fill[i]   = r;
        if (i == 0) g_rowptr[n] = E;
    }
}
__global__ void k_scatter(const int* __restrict__ ei, int E) {
    int e = blockIdx.x * blockDim.x + threadIdx.x;
    if (e < E) {
        int pos = atomicAdd(&g_fill[ei[E + e]], 1);
        g_csr[pos] = ei[e];
    }
}

// ---- scalar GEMM mainloop: 64 rows/block, 8 rows/warp, fp16 out ----------
// NOTE: no dinv scale here — messages are unscaled.
__device__ __forceinline__ void gemm_main(const float (*sx)[D],
                                          const float* __restrict__ W,
                                          __half* __restrict__ out, int base, int n)
{
    int t = threadIdx.x, warp = t >> 5, lane = t & 31;
    int r0 = warp * 8;
    float4 acc[8];
    #pragma unroll
    for (int r = 0; r < 8; r++) acc[r] = make_float4(0.f, 0.f, 0.f, 0.f);

    const float* Wp = W + lane * 4;
    #pragma unroll 4
    for (int k = 0; k < D; k++) {
        float4 w = *(const float4*)(Wp + k * D);
        #pragma unroll
        for (int r = 0; r < 8; r++) {
            float xv = sx[r0 + r][k];
            acc[r].x = fmaf(xv, w.x, acc[r].x);
            acc[r].y = fmaf(xv, w.y, acc[r].y);
            acc[r].z = fmaf(xv, w.z, acc[r].z);
            acc[r].w = fmaf(xv, w.w, acc[r].w);
        }
    }
    #pragma unroll
    for (int r = 0; r < 8; r++) {
        int row = base + r0 + r;
        if (row < n) {
            uint2 st;
            st.x = pack_h2(acc[r].x, acc[r].y);
            st.y = pack_h2(acc[r].z, acc[r].w);
            *(uint2*)(out + (size_t)row * D + lane * 4) = st;
        }
    }
}

// ---- layer 1 GEMM: g_hs = x @ W1  (independent of CSR/dinv!) -------------
__global__ void __launch_bounds__(256)
k_gemm1(const float* __restrict__ in, const float* __restrict__ W, int n)
{
    __shared__ float sx[64][D];
    int t = threadIdx.x;
    int base = blockIdx.x * 64;
    #pragma unroll
    for (int j = 0; j < 8; j++) {
        int f = j * 256 + t;
        int r = f >> 5, c = f & 31;
        int row = base + r;
        if (row < n)
            *(float4*)&sx[r][c * 4] = *(const float4*)(in + (size_t)row * D + c * 4);
    }
    __syncthreads();
    gemm_main(sx, W, g_hs, base, n);
}

// ---- layer 2 GEMM: reads g_agg, applies relu(dinv*agg+b1), -> g_hs -------
__global__ void __launch_bounds__(256)
k_gemm2(const float* __restrict__ b1, const float* __restrict__ W, int n)
{
    __shared__ float sx[64][D];
    int t = threadIdx.x;
    int base = blockIdx.x * 64;
    #pragma unroll
    for (int j = 0; j < 8; j++) {
        int f = j * 256 + t;
        int r = f >> 5, c = f & 31;
        int row = base + r;
        if (row < n) {
            float  di = g_dinv[row];
            float4 a  = *(const float4*)(g_agg + (size_t)row * D + c * 4);
            float4 b  = *(const float4*)(b1 + c * 4);
            float4 v;
            v.x = fmaxf(fmaf(di, a.x, b.x), 0.0f);
            v.y = fmaxf(fmaf(di, a.y, b.y), 0.0f);
            v.z = fmaxf(fmaf(di, a.z, b.z), 0.0f);
            v.w = fmaxf(fmaf(di, a.w, b.w), 0.0f);
            *(float4*)&sx[r][c * 4] = v;
        }
    }
    __syncthreads();
    gemm_main(sx, W, g_hs, base, n);                   // ping-pong -> g_hs
}

// ---- gather body: fp16 messages * dinv[src], fp32 accumulate, MLP=8 ------
__device__ __forceinline__ float4 gather_rows(float4 acc, int e, int end, int lane)
{
    for (; e + 7 < end; e += 8) {
        int s0 = g_csr[e],   s1 = g_csr[e+1], s2 = g_csr[e+2], s3 = g_csr[e+3];
        int s4 = g_csr[e+4], s5 = g_csr[e+5], s6 = g_csr[e+6], s7 = g_csr[e+7];
        uint2 u0 = *(const uint2*)(g_hs + (size_t)s0 * D + lane * 4);
        uint2 u1 = *(const uint2*)(g_hs + (size_t)s1 * D + lane * 4);
        uint2 u2 = *(const uint2*)(g_hs + (size_t)s2 * D + lane * 4);
        uint2 u3 = *(const uint2*)(g_hs + (size_t)s3 * D + lane * 4);
        uint2 u4 = *(const uint2*)(g_hs + (size_t)s4 * D + lane * 4);
        uint2 u5 = *(const uint2*)(g_hs + (size_t)s5 * D + lane * 4);
        uint2 u6 = *(const uint2*)(g_hs + (size_t)s6 * D + lane * 4);
        uint2 u7 = *(const uint2*)(g_hs + (size_t)s7 * D + lane * 4);
        float d0 = g_dinv[s0], d1 = g_dinv[s1], d2 = g_dinv[s2], d3 = g_dinv[s3];
        float d4 = g_dinv[s4], d5 = g_dinv[s5], d6 = g_dinv[s6], d7 = g_dinv[s7];
        float2 a, b;
        a = unpack_h2(u0.x); b = unpack_h2(u0.y);
        acc.x = fmaf(a.x, d0, acc.x); acc.y = fmaf(a.y, d0, acc.y);
        acc.z = fmaf(b.x, d0, acc.z); acc.w = fmaf(b.y, d0, acc.w);
        a = unpack_h2(u1.x); b = unpack_h2(u1.y);
        acc.x = fmaf(a.x, d1, acc.x); acc.y = fmaf(a.y, d1, acc.y);
        acc.z = fmaf(b.x, d1, acc.z); acc.w = fmaf(b.y, d1, acc.w);
        a = unpack_h2(u2.x); b = unpack_h2(u2.y);
        acc.x = fmaf(a.x, d2, acc.x); acc.y = fmaf(a.y, d2, acc.y);
        acc.z = fmaf(b.x, d2, acc.z); acc.w = fmaf(b.y, d2, acc.w);
        a = unpack_h2(u3.x); b = unpack_h2(u3.y);
        acc.x = fmaf(a.x, d3, acc.x); acc.y = fmaf(a.y, d3, acc.y);
        acc.z = fmaf(b.x, d3, acc.z); acc.w = fmaf(b.y, d3, acc.w);
        a = unpack_h2(u4.x); b = unpack_h2(u4.y);
        acc.x = fmaf(a.x, d4, acc.x); acc.y = fmaf(a.y, d4, acc.y);
        acc.z = fmaf(b.x, d4, acc.z); acc.w = fmaf(b.y, d4, acc.w);
        a = unpack_h2(u5.x); b = unpack_h2(u5.y);
        acc.x = fmaf(a.x, d5, acc.x); acc.y = fmaf(a.y, d5, acc.y);
        acc.z = fmaf(b.x, d5, acc.z); acc.w = fmaf(b.y, d5, acc.w);
        a = unpack_h2(u6.x); b = unpack_h2(u6.y);
        acc.x = fmaf(a.x, d6, acc.x); acc.y = fmaf(a.y, d6, acc.y);
        acc.z = fmaf(b.x, d6, acc.z); acc.w = fmaf(b.y, d6, acc.w);
        a = unpack_h2(u7.x); b = unpack_h2(u7.y);
        acc.x = fmaf(a.x, d7, acc.x); acc.y = fmaf(a.y, d7, acc.y);
        acc.z = fmaf(b.x, d7, acc.z); acc.w = fmaf(b.y, d7, acc.w);
    }
    for (; e < end; e++) {
        int s0 = g_csr[e];
        uint2 u0 = *(const uint2*)(g_hs + (size_t)s0 * D + lane * 4);
        float d0 = g_dinv[s0];
        float2 a = unpack_h2(u0.x), b = unpack_h2(u0.y);
        acc.x = fmaf(a.x, d0, acc.x); acc.y = fmaf(a.y, d0, acc.y);
        acc.z = fmaf(b.x, d0, acc.z); acc.w = fmaf(b.y, d0, acc.w);
    }
    return acc;
}

// ---- aggregation: g_agg[i] = sum m[src]*dinv[src] (incl self) ------------
__global__ void __launch_bounds__(256)
k_agg(int n)
{
    int w    = (blockIdx.x * blockDim.x + threadIdx.x) >> 5;
    int lane = threadIdx.x & 31;
    if (w >= n) return;
    uint2 su = *(const uint2*)(g_hs + (size_t)w * D + lane * 4);
    float ds = g_dinv[w];
    float2 sa = unpack_h2(su.x), sb = unpack_h2(su.y);
    float4 acc = make_float4(sa.x * ds, sa.y * ds, sb.x * ds, sb.y * ds);
    acc = gather_rows(acc, g_rowptr[w], g_rowptr[w + 1], lane);
    *(float4*)(g_agg + (size_t)w * D + lane * 4) = acc;
}

// ---- final aggregation + heads -------------------------------------------
__global__ void __launch_bounds__(256)
k_agg_heads(const float* __restrict__ b2,
            const float* __restrict__ Wt, const float* __restrict__ bt,
            const float* __restrict__ We, const float* __restrict__ be,
            float* __restrict__ out, int n)
{
    int w    = (blockIdx.x * blockDim.x + threadIdx.x) >> 5;
    int lane = threadIdx.x & 31;
    if (w >= n) return;

    uint2 su = *(const uint2*)(g_hs + (size_t)w * D + lane * 4);
    float ds = g_dinv[w];
    float2 sa = unpack_h2(su.x), sb = unpack_h2(su.y);
    float4 acc = make_float4(sa.x * ds, sa.y * ds, sb.x * ds, sb.y * ds);
    acc = gather_rows(acc, g_rowptr[w], g_rowptr[w + 1], lane);

    float  di = g_dinv[w];
    float4 b  = *(const float4*)(b2 + lane * 4);
    float4 h;
    h.x = fmaxf(fmaf(di, acc.x, b.x), 0.0f);
    h.y = fmaxf(fmaf(di, acc.y, b.y), 0.0f);
    h.z = fmaxf(fmaf(di, acc.z, b.z), 0.0f);
    h.w = fmaxf(fmaf(di, acc.w, b.w), 0.0f);

    float4 wt = *(const float4*)(Wt + lane * 4);
    float4 we = *(const float4*)(We + lane * 4);
    float st = h.x*wt.x + h.y*wt.y + h.z*wt.z + h.w*wt.w;
    float ev = h.x*we.x + h.y*we.y + h.z*we.z + h.w*we.w;
    #pragma unroll
    for (int off = 16; off; off >>= 1) {
        st += __shfl_xor_sync(0xFFFFFFFFu, st, off);
        ev += __shfl_xor_sync(0xFFFFFFFFu, ev, off);
    }
    if (lane == 0) {
        out[w]     = st + bt[0];
        out[n + w] = ev + be[0];
    }
}

// ---------------------------------------------------------------------------
extern "C" void kernel_launch(void* const* d_in, const int* in_sizes, int n_in,
                              void* d_out, int out_size)
{
    const float* x   = (const float*)d_in[0];
    const int*   ei  = (const int*)  d_in[1];
    const float* W1  = (const float*)d_in[2];
    const float* b1  = (const float*)d_in[3];
    const float* W2  = (const float*)d_in[4];
    const float* b2  = (const float*)d_in[5];
    const float* Wt  = (const float*)d_in[6];
    const float* bt  = (const float*)d_in[7];
    const float* We  = (const float*)d_in[8];
    const float* be  = (const float*)d_in[9];
    float* out = (float*)d_out;

    int n = in_sizes[0] / D;       // 50000
    int E = in_sizes[1] / 2;       // 800000

    const int T = 256;
    int nb_n = (n + T - 1) / T;
    int nb_e = (E + T - 1) / T;
    int nb_g = (n + 63) / 64;
    int nb_w = (n + 7) / 8;

    // one-time side-stream + fork/join events (host resources only; created
    // on the first, non-captured correctness call)
    static cudaStream_t s2 = nullptr;
    static cudaEvent_t  evFork = nullptr, evJoin = nullptr;
    if (s2 == nullptr) {
        cudaStreamCreateWithFlags(&s2, cudaStreamNonBlocking);
        cudaEventCreateWithFlags(&evFork, cudaEventDisableTiming);
        cudaEventCreateWithFlags(&evJoin, cudaEventDisableTiming);
    }

    // fork: CSR/degree build on s2, layer-1 GEMM on the main stream
    cudaEventRecord(evFork, 0);
    cudaStreamWaitEvent(s2, evFork, 0);

    k_zero     <<<nb_n, T, 0, s2>>>(n);
    k_count_deg<<<nb_e, T, 0, s2>>>(ei, E);
    k_scan1    <<<nb_n, T, 0, s2>>>(n);
    k_scan3    <<<nb_n, T, 0, s2>>>(n, E, nb_n);
    k_scatter  <<<nb_e, T, 0, s2>>>(ei, E);

    k_gemm1<<<nb_g, T>>>(x, W1, n);        // main stream, runs concurrently

    // join
    cudaEventRecord(evJoin, s2);
    cudaStreamWaitEvent(0, evJoin, 0);

    // layer 1 aggregation -> g_agg
    k_agg<<<nb_w, T>>>(n);

    // layer 2: (relu transform + GEMM) -> g_hs, aggregate + heads -> out
    k_gemm2    <<<nb_g, T>>>(b1, W2, n);
    k_agg_heads<<<nb_w, T>>>(b2, Wt, bt, We, be, out, n);
}